// round 2
// baseline (speedup 1.0000x reference)
#include <cuda_runtime.h>

#define B   64
#define T   100
#define NI  700
#define NH  512
#define NO  20
#define TAUc 0.6f
#define KAPc 0.6f
#define THRc 0.6f
#define LRc  0.05f

// ---------------- persistent device scratch (allowed: __device__ globals) ----------------
__device__ float g_hm[B*NH];
__device__ float g_hs[B*NH];      // z_{t-1}
__device__ float g_om[B*NO];
__device__ float g_os[B*NO];
__device__ float g_tin[B*NI];
__device__ float g_trec[B*NH];
__device__ float g_part[5][B*NH]; // split-K partials of hidden input

__device__ float g_TIN [T*B*NI];  // stored traces (time-major)
__device__ float g_TREC[T*B*NH];
__device__ float g_HT  [T*B*NH];
__device__ float g_Z   [T*B*NH];
__device__ float g_ERR [T*B*NO];
__device__ float g_EF  [T*B*NO];  // reverse-filtered error
__device__ float g_A   [T*B*NH];  // (errfilt @ w_out) * h_t
__device__ float g_gpart[4*512*700]; // GEMM split-K partials (max: gf KS=4)

// ---------------- init ----------------
__global__ void k_init() {
    int i = blockIdx.x * blockDim.x + threadIdx.x;
    if (i < B*NH) { g_hm[i] = 0.f; g_hs[i] = 0.f; g_trec[i] = 0.f; }
    if (i < B*NO) { g_om[i] = 0.f; g_os[i] = 0.f; }
    if (i < B*NI) { g_tin[i] = 0.f; }
}

// ---------------- per-step hidden-input GEMM (split-K into 5 chunks) ----------------
// hidden_input[b][r] = sum_i x_t[b,i]*W1[r,i]  +  sum_j z_{t-1}[b,j]*Wrec[j,r]
// chunks 0-2: x part (k in [0,234),[234,468),[468,700)); chunks 3-4: rec part (k in [0,256),[256,512))
__global__ void k_gemmH(const float* __restrict__ x, const float* __restrict__ w1,
                        const float* __restrict__ wrec, int t) {
    __shared__ float As[16][65];   // [k][b]
    __shared__ float Bs[16][33];   // [k][r]
    int chunk = blockIdx.y;
    int r0 = blockIdx.x * 32;
    int tid = threadIdx.x;
    int tx = tid & 31, ty = tid >> 5;

    int ks, ke, mode;
    if (chunk < 3) {
        const int xc0[4] = {0, 234, 468, 700};
        ks = xc0[chunk]; ke = xc0[chunk + 1]; mode = 0;
    } else {
        ks = (chunk - 3) * 256; ke = ks + 256; mode = 1;
    }

    float acc[8];
#pragma unroll
    for (int u = 0; u < 8; u++) acc[u] = 0.f;

    for (int k0 = ks; k0 < ke; k0 += 16) {
        // load A tile: As[kk][b]
#pragma unroll
        for (int rep = 0; rep < 4; rep++) {
            int e = tid + rep * 256;           // 0..1023
            int kk = e & 15, b = e >> 4;
            int kg = k0 + kk;
            float v = 0.f;
            if (kg < ke) v = (mode == 0) ? x[(b * T + t) * NI + kg]
                                         : g_hs[b * NH + kg];
            As[kk][b] = v;
        }
        // load B tile: Bs[kk][rr]
        if (mode == 0) {
#pragma unroll
            for (int rep = 0; rep < 2; rep++) {
                int e = tid + rep * 256;       // 0..511
                int kk = e & 15, rr = e >> 4;
                int kg = k0 + kk;
                Bs[kk][rr] = (kg < ke) ? w1[(r0 + rr) * NI + kg] : 0.f;
            }
        } else {
#pragma unroll
            for (int rep = 0; rep < 2; rep++) {
                int e = tid + rep * 256;
                int rr = e & 31, kk = e >> 5;
                int kg = k0 + kk;
                Bs[kk][rr] = (kg < ke) ? wrec[kg * NH + r0 + rr] : 0.f;
            }
        }
        __syncthreads();
#pragma unroll
        for (int k = 0; k < 16; k++) {
            float bv = Bs[k][tx];
#pragma unroll
            for (int u = 0; u < 8; u++) acc[u] += As[k][ty * 8 + u] * bv;
        }
        __syncthreads();
    }
#pragma unroll
    for (int u = 0; u < 8; u++) {
        int b = ty * 8 + u;
        g_part[chunk][b * NH + r0 + tx] = acc[u];
    }
}

// ---------------- per-step fused pointwise + output stage ----------------
// one block per batch sample; 640 threads (20 warps)
__global__ void k_rest(const float* __restrict__ x, const float* __restrict__ label,
                       const float* __restrict__ wout, float* __restrict__ out, int t) {
    int b = blockIdx.x;
    int tid = threadIdx.x;
    __shared__ float zsh[NH];

    if (tid < NH) {
        int idx = b * NH + tid;
        float hid = g_part[0][idx] + g_part[1][idx] + g_part[2][idx]
                  + g_part[3][idx] + g_part[4][idx];
        float hsp = g_hs[idx];
        float hm  = TAUc * g_hm[idx] * (1.f - hsp) + hid;
        float z   = (hm >= THRc) ? 1.f : 0.f;
        float ht  = TAUc * fmaxf(0.f, 1.f - fabsf((hm - THRc) / THRc));
        float tr  = TAUc * g_trec[idx] + hsp;           // trace_rec uses z_{t-1}
        g_hm[idx] = hm; g_hs[idx] = z; g_trec[idx] = tr;
        int sidx = (t * B + b) * NH + tid;
        g_TREC[sidx] = tr; g_HT[sidx] = ht; g_Z[sidx] = z;
        zsh[tid] = z;
    }
    // input trace
    for (int i = tid; i < NI; i += blockDim.x) {
        int idx = b * NI + i;
        float tv = TAUc * g_tin[idx] + x[(b * T + t) * NI + i];
        g_tin[idx] = tv;
        g_TIN[(t * B + b) * NI + i] = tv;
    }
    __syncthreads();
    // output LIF: warp w computes output neuron w
    int w = tid >> 5, lane = tid & 31;
    if (w < NO) {
        float s = 0.f;
        for (int r = lane; r < NH; r += 32) s += zsh[r] * wout[w * NH + r];
#pragma unroll
        for (int off = 16; off; off >>= 1) s += __shfl_down_sync(0xffffffffu, s, off);
        if (lane == 0) {
            int oi = b * NO + w;
            float osp = g_os[oi];
            float om  = TAUc * g_om[oi] * (1.f - osp) + s;
            float osn = (om >= THRc) ? 1.f : 0.f;
            g_om[oi] = om; g_os[oi] = osn;
            float err = osn - label[(b * T + t) * NO + w];
            g_ERR[(t * B + b) * NO + w] = err;
            out[(b * T + t) * NO + w] = osn;
        }
    }
}

// ---------------- reverse-time kappa filter of err ----------------
__global__ void k_revfilt() {
    int tid = threadIdx.x;
    for (int idx = tid; idx < B * NO; idx += blockDim.x) {
        float ef = 0.f;
        for (int t = T - 1; t >= 0; t--) {
            ef = g_ERR[t * B * NO + idx] + KAPc * ef;
            g_EF[t * B * NO + idx] = ef;
        }
    }
}

// ---------------- A[m,r] = (EF[m,:] . wout[:,r]) * HT[m,r] ----------------
__global__ void k_A(const float* __restrict__ wout) {
    int gid = blockIdx.x * 256 + threadIdx.x;
    if (gid >= T * B * NH) return;
    int m = gid >> 9;     // / NH
    int r = gid & (NH - 1);
    const float* ef = g_EF + m * NO;
    float L = 0.f;
#pragma unroll
    for (int o = 0; o < NO; o++) L += ef[o] * wout[o * NH + r];
    g_A[gid] = L * g_HT[gid];
}

// ---------------- generic C = A^T B with split-K partials ----------------
// A: [K, M] row-major (stride sA), B: [K, N] row-major (stride sB)
// Cp[z] gets the partial for k-range z. Tiles 64x64x16, 256 threads, 4x4 microtile.
__global__ void k_gemmT(const float* __restrict__ A, int sA,
                        const float* __restrict__ Bm, int sB,
                        float* __restrict__ Cp,
                        int M, int N, int K, int kchunk) {
    __shared__ float As[16][64];
    __shared__ float Bs[16][64];
    int m0 = blockIdx.y * 64, n0 = blockIdx.x * 64;
    int z = blockIdx.z;
    int k0s = z * kchunk;
    int k0e = min(K, k0s + kchunk);
    int tid = threadIdx.x;
    int tx = tid & 15, ty = tid >> 4;
    float acc[4][4] = {};
    for (int k0 = k0s; k0 < k0e; k0 += 16) {
#pragma unroll
        for (int rep = 0; rep < 4; rep++) {
            int e = tid + rep * 256;
            int mm = e & 63, kk = e >> 6;
            int mg = m0 + mm;
            As[kk][mm] = (mg < M) ? A[(k0 + kk) * sA + mg] : 0.f;
            int ng = n0 + mm;
            Bs[kk][mm] = (ng < N) ? Bm[(k0 + kk) * sB + ng] : 0.f;
        }
        __syncthreads();
#pragma unroll
        for (int k = 0; k < 16; k++) {
            float a[4], bb[4];
#pragma unroll
            for (int i = 0; i < 4; i++) a[i]  = As[k][ty * 4 + i];
#pragma unroll
            for (int j = 0; j < 4; j++) bb[j] = Bs[k][tx * 4 + j];
#pragma unroll
            for (int i = 0; i < 4; i++)
#pragma unroll
                for (int j = 0; j < 4; j++) acc[i][j] += a[i] * bb[j];
        }
        __syncthreads();
    }
    float* C = Cp + (size_t)z * M * N;
#pragma unroll
    for (int i = 0; i < 4; i++) {
        int m = m0 + ty * 4 + i;
        if (m < M) {
#pragma unroll
            for (int j = 0; j < 4; j++) {
                int n = n0 + tx * 4 + j;
                if (n < N) C[m * N + n] = acc[i][j];
            }
        }
    }
}

__global__ void k_reduce(const float* __restrict__ Cp, float* __restrict__ out,
                         int MN, int KS) {
    int i = blockIdx.x * 256 + threadIdx.x;
    if (i >= MN) return;
    float s = 0.f;
    for (int z = 0; z < KS; z++) s += Cp[z * MN + i];
    out[i] = LRc * s;
}

// ---------------- launch ----------------
extern "C" void kernel_launch(void* const* d_in, const int* in_sizes, int n_in,
                              void* d_out, int out_size) {
    const float* x     = (const float*)d_in[0];
    const float* label = (const float*)d_in[1];
    const float* w1    = (const float*)d_in[3];
    const float* wrec  = (const float*)d_in[4];
    const float* wout  = (const float*)d_in[5];
    float* out = (float*)d_out;
    float* gf = out + B * T * NO;          // [NH, NI]
    float* gr = gf + NH * NI;              // [NH, NH]
    float* go = gr + NH * NH;              // [NO, NH]

    float *pA, *pTIN, *pTREC, *pZ, *pEF, *pGP;
    cudaGetSymbolAddress((void**)&pA,    g_A);
    cudaGetSymbolAddress((void**)&pTIN,  g_TIN);
    cudaGetSymbolAddress((void**)&pTREC, g_TREC);
    cudaGetSymbolAddress((void**)&pZ,    g_Z);
    cudaGetSymbolAddress((void**)&pEF,   g_EF);
    cudaGetSymbolAddress((void**)&pGP,   g_gpart);

    k_init<<<(B * NI + 255) / 256, 256>>>();

    for (int t = 0; t < T; t++) {
        k_gemmH<<<dim3(16, 5), 256>>>(x, w1, wrec, t);
        k_rest<<<B, 640>>>(x, label, wout, out, t);
    }

    k_revfilt<<<1, 1024>>>();
    k_A<<<(T * B * NH + 255) / 256, 256>>>(wout);

    // gf = LR * A^T @ TIN   [512 x 700], K = 6400, split-K 4
    k_gemmT<<<dim3(11, 8, 4), 256>>>(pA, NH, pTIN, NI, pGP, NH, NI, T * B, 1600);
    k_reduce<<<(NH * NI + 255) / 256, 256>>>(pGP, gf, NH * NI, 4);

    // gr = LR * A^T @ TREC  [512 x 512], K = 6400, split-K 4
    k_gemmT<<<dim3(8, 8, 4), 256>>>(pA, NH, pTREC, NH, pGP, NH, NH, T * B, 1600);
    k_reduce<<<(NH * NH + 255) / 256, 256>>>(pGP, gr, NH * NH, 4);

    // go = LR * EF^T @ Z    [20 x 512], K = 6400, split-K 8
    k_gemmT<<<dim3(8, 1, 8), 256>>>(pEF, NO, pZ, NH, pGP, NO, NH, T * B, 800);
    k_reduce<<<(NO * NH + 255) / 256, 256>>>(pGP, go, NO * NH, 8);
}

// round 3
// speedup vs baseline: 3.3668x; 3.3668x over previous
#include <cuda_runtime.h>

#define B   64
#define T   100
#define NI  700
#define NH  512
#define NO  20
#define TAUc 0.6f
#define KAPc 0.6f
#define THRc 0.6f
#define LRc  0.05f

#define NBLK 128   // persistent forward blocks (8 b-groups x 16 r-groups)

// ---------------- persistent device scratch ----------------
__device__ float g_XP  [T*B*NH];   // x @ W1^T, time-major rows m = t*B+b
__device__ float g_TIN [T*B*NI];
__device__ float g_TREC[T*B*NH];
__device__ float g_HT  [T*B*NH];
__device__ float g_Z   [T*B*NH];
__device__ float g_ERR [T*B*NO];
__device__ float g_EF  [T*B*NO];
__device__ float g_A   [T*B*NH];
__device__ float g_gpart[4*512*700];
__device__ unsigned g_barc, g_barg;

// ---------------- tin scan (no recurrence) + barrier init ----------------
__global__ void k_tin(const float* __restrict__ x) {
    int n = blockIdx.x * blockDim.x + threadIdx.x;
    if (n == 0) { g_barc = 0u; g_barg = 0u; }
    if (n >= B * NI) return;
    int b = n / NI, i = n - b * NI;
    float tv = 0.f;
    for (int t = 0; t < T; t++) {
        tv = TAUc * tv + x[(b * T + t) * NI + i];
        g_TIN[((size_t)t * B + b) * NI + i] = tv;
    }
}

// ---------------- Xproj = X @ W1^T : [6400,512], K=700 ----------------
__global__ void k_gemmX(const float* __restrict__ x, const float* __restrict__ w1) {
    __shared__ float As[16][65];
    __shared__ float Bs[16][65];
    int m0 = blockIdx.y * 64, n0 = blockIdx.x * 64;
    int tid = threadIdx.x;
    int tx = tid & 15, ty = tid >> 4;
    float acc[4][4] = {};
    for (int k0 = 0; k0 < NI; k0 += 16) {
#pragma unroll
        for (int rep = 0; rep < 4; rep++) {
            int e = tid + rep * 256;
            int kk = e & 15, mm = e >> 4;
            int kg = k0 + kk;
            int m = m0 + mm, bb = m & 63, tt = m >> 6;
            As[kk][mm] = (kg < NI) ? x[(bb * T + tt) * NI + kg] : 0.f;
            Bs[kk][mm] = (kg < NI) ? w1[(n0 + mm) * NI + kg] : 0.f;
        }
        __syncthreads();
#pragma unroll
        for (int k = 0; k < 16; k++) {
            float a[4], bb4[4];
#pragma unroll
            for (int i = 0; i < 4; i++) a[i]   = As[k][ty * 4 + i];
#pragma unroll
            for (int j = 0; j < 4; j++) bb4[j] = Bs[k][tx * 4 + j];
#pragma unroll
            for (int i = 0; i < 4; i++)
#pragma unroll
                for (int j = 0; j < 4; j++) acc[i][j] += a[i] * bb4[j];
        }
        __syncthreads();
    }
#pragma unroll
    for (int i = 0; i < 4; i++) {
        int m = m0 + ty * 4 + i;
#pragma unroll
        for (int j = 0; j < 4; j++)
            g_XP[(size_t)m * NH + n0 + tx * 4 + j] = acc[i][j];
    }
}

// ---------------- persistent forward: 100 steps, 1 grid barrier/step ----------------
// block = (bg in 0..7, rg in 0..15). warp ty owns b = bg*8+ty, lane owns r = rg*32+lane.
// hm / trec / z_prev live in registers. Wrec column slice lives in smem (64KB).
__global__ void k_forward(const float* __restrict__ wrec) {
    extern __shared__ float Ws[];   // [512][32] = Wrec[:, r0:r0+32]
    int bg = blockIdx.x & 7, rg = blockIdx.x >> 3;
    int tid = threadIdx.x, lane = tid & 31, ty = tid >> 5;
    int b = bg * 8 + ty;
    int r0 = rg * 32;
    int r = r0 + lane;

    for (int idx = tid; idx < NH * 32; idx += 256)
        Ws[idx] = wrec[(idx >> 5) * NH + r0 + (idx & 31)];
    __syncthreads();

    float hm = 0.f, tr = 0.f, zs = 0.f;

    for (int t = 0; t < T; t++) {
        float acc = 0.f;
        if (t > 0) {
            const float* zp = g_Z + ((size_t)(t - 1) * B + b) * NH;
            float zv[16];
#pragma unroll
            for (int c = 0; c < 16; c++) zv[c] = __ldcg(zp + c * 32 + lane);
#pragma unroll
            for (int c = 0; c < 16; c++) {
                unsigned m = __ballot_sync(0xffffffffu, zv[c] != 0.f);
                while (m) {
                    int j = c * 32 + (__ffs(m) - 1);
                    m &= m - 1;
                    acc += Ws[j * 32 + lane];
                }
            }
        }
        float hid = __ldcg(&g_XP[((size_t)t * B + b) * NH + r]) + acc;
        hm = TAUc * hm * (1.f - zs) + hid;
        float z  = (hm >= THRc) ? 1.f : 0.f;
        float ht = TAUc * fmaxf(0.f, 1.f - fabsf((hm - THRc) * (1.f / THRc)));
        tr = TAUc * tr + zs;                 // trace_rec uses z_{t-1}
        size_t o = ((size_t)t * B + b) * NH + r;
        g_Z[o] = z; g_HT[o] = ht; g_TREC[o] = tr;
        zs = z;

        // ---- software grid barrier ----
        __syncthreads();
        if (tid == 0) {
            __threadfence();
            unsigned gen = *(volatile unsigned*)&g_barg;
            if (atomicAdd(&g_barc, 1u) == NBLK - 1) {
                g_barc = 0u;
                __threadfence();
                atomicAdd(&g_barg, 1u);
            } else {
                while (*(volatile unsigned*)&g_barg == gen) { }
            }
        }
        __syncthreads();
    }
}

// ---------------- output LIF chain (no feedback into hidden) ----------------
__global__ void k_out(const float* __restrict__ label, const float* __restrict__ wout,
                      float* __restrict__ out) {
    __shared__ float ws[NO * NH];   // 40KB
    __shared__ float zrow[NH];
    int b = blockIdx.x;
    int tid = threadIdx.x;          // 640 = 20 warps
    int w = tid >> 5, lane = tid & 31;
    for (int idx = tid; idx < NO * NH; idx += 640) ws[idx] = wout[idx];
    float om = 0.f, os = 0.f;
    __syncthreads();
    for (int t = 0; t < T; t++) {
        for (int idx = tid; idx < NH; idx += 640)
            zrow[idx] = g_Z[((size_t)t * B + b) * NH + idx];
        __syncthreads();
        float s = 0.f;
#pragma unroll
        for (int c = 0; c < 16; c++) s += zrow[lane + c * 32] * ws[w * NH + lane + c * 32];
#pragma unroll
        for (int off = 16; off; off >>= 1) s += __shfl_down_sync(0xffffffffu, s, off);
        if (lane == 0) {
            om = TAUc * om * (1.f - os) + s;
            os = (om >= THRc) ? 1.f : 0.f;
            float err = os - label[(b * T + t) * NO + w];
            out[(b * T + t) * NO + w] = os;
            g_ERR[((size_t)t * B + b) * NO + w] = err;
        }
        __syncthreads();
    }
}

// ---------------- reverse-time kappa filter of err ----------------
__global__ void k_revfilt() {
    int tid = threadIdx.x;
    for (int idx = tid; idx < B * NO; idx += blockDim.x) {
        float ef = 0.f;
        for (int t = T - 1; t >= 0; t--) {
            ef = g_ERR[(size_t)t * B * NO + idx] + KAPc * ef;
            g_EF[(size_t)t * B * NO + idx] = ef;
        }
    }
}

// ---------------- A[m,r] = (EF[m,:] . wout[:,r]) * HT[m,r] ----------------
__global__ void k_A(const float* __restrict__ wout) {
    int gid = blockIdx.x * 256 + threadIdx.x;
    if (gid >= T * B * NH) return;
    int m = gid >> 9;
    int r = gid & (NH - 1);
    const float* ef = g_EF + (size_t)m * NO;
    float L = 0.f;
#pragma unroll
    for (int o = 0; o < NO; o++) L += ef[o] * wout[o * NH + r];
    g_A[gid] = L * g_HT[gid];
}

// ---------------- C = A^T B with split-K partials (64x64x16 tiles) ----------------
__global__ void k_gemmT(const float* __restrict__ A, int sA,
                        const float* __restrict__ Bm, int sB,
                        float* __restrict__ Cp,
                        int M, int N, int K, int kchunk) {
    __shared__ float As[16][64];
    __shared__ float Bs[16][64];
    int m0 = blockIdx.y * 64, n0 = blockIdx.x * 64;
    int z = blockIdx.z;
    int k0s = z * kchunk;
    int k0e = min(K, k0s + kchunk);
    int tid = threadIdx.x;
    int tx = tid & 15, ty = tid >> 4;
    float acc[4][4] = {};
    for (int k0 = k0s; k0 < k0e; k0 += 16) {
#pragma unroll
        for (int rep = 0; rep < 4; rep++) {
            int e = tid + rep * 256;
            int mm = e & 63, kk = e >> 6;
            int mg = m0 + mm;
            As[kk][mm] = (mg < M) ? A[(size_t)(k0 + kk) * sA + mg] : 0.f;
            int ng = n0 + mm;
            Bs[kk][mm] = (ng < N) ? Bm[(size_t)(k0 + kk) * sB + ng] : 0.f;
        }
        __syncthreads();
#pragma unroll
        for (int k = 0; k < 16; k++) {
            float a[4], bb[4];
#pragma unroll
            for (int i = 0; i < 4; i++) a[i]  = As[k][ty * 4 + i];
#pragma unroll
            for (int j = 0; j < 4; j++) bb[j] = Bs[k][tx * 4 + j];
#pragma unroll
            for (int i = 0; i < 4; i++)
#pragma unroll
                for (int j = 0; j < 4; j++) acc[i][j] += a[i] * bb[j];
        }
        __syncthreads();
    }
    float* C = Cp + (size_t)z * M * N;
#pragma unroll
    for (int i = 0; i < 4; i++) {
        int m = m0 + ty * 4 + i;
        if (m < M) {
#pragma unroll
            for (int j = 0; j < 4; j++) {
                int n = n0 + tx * 4 + j;
                if (n < N) C[(size_t)m * N + n] = acc[i][j];
            }
        }
    }
}

__global__ void k_reduce(const float* __restrict__ Cp, float* __restrict__ out,
                         int MN, int KS) {
    int i = blockIdx.x * 256 + threadIdx.x;
    if (i >= MN) return;
    float s = 0.f;
    for (int z = 0; z < KS; z++) s += Cp[(size_t)z * MN + i];
    out[i] = LRc * s;
}

// ---------------- launch ----------------
extern "C" void kernel_launch(void* const* d_in, const int* in_sizes, int n_in,
                              void* d_out, int out_size) {
    const float* x     = (const float*)d_in[0];
    const float* label = (const float*)d_in[1];
    const float* w1    = (const float*)d_in[3];
    const float* wrec  = (const float*)d_in[4];
    const float* wout  = (const float*)d_in[5];
    float* out = (float*)d_out;
    float* gf = out + B * T * NO;          // [NH, NI]
    float* gr = gf + NH * NI;              // [NH, NH]
    float* go = gr + NH * NH;              // [NO, NH]

    static int attr_done = 0;
    if (!attr_done) {
        cudaFuncSetAttribute(k_forward, cudaFuncAttributeMaxDynamicSharedMemorySize,
                             NH * 32 * (int)sizeof(float));
        attr_done = 1;
    }

    float *pA, *pTIN, *pTREC, *pZ, *pEF, *pGP;
    cudaGetSymbolAddress((void**)&pA,    g_A);
    cudaGetSymbolAddress((void**)&pTIN,  g_TIN);
    cudaGetSymbolAddress((void**)&pTREC, g_TREC);
    cudaGetSymbolAddress((void**)&pZ,    g_Z);
    cudaGetSymbolAddress((void**)&pEF,   g_EF);
    cudaGetSymbolAddress((void**)&pGP,   g_gpart);

    k_tin<<<(B * NI + 255) / 256, 256>>>(x);
    k_gemmX<<<dim3(8, 100), 256>>>(x, w1);
    k_forward<<<NBLK, 256, NH * 32 * sizeof(float)>>>(wrec);
    k_out<<<B, 640>>>(label, wout, out);
    k_revfilt<<<1, 1024>>>();
    k_A<<<(T * B * NH + 255) / 256, 256>>>(wout);

    // gf = LR * A^T @ TIN   [512 x 700], K = 6400
    k_gemmT<<<dim3(11, 8, 4), 256>>>(pA, NH, pTIN, NI, pGP, NH, NI, T * B, 1600);
    k_reduce<<<(NH * NI + 255) / 256, 256>>>(pGP, gf, NH * NI, 4);

    // gr = LR * A^T @ TREC  [512 x 512], K = 6400
    k_gemmT<<<dim3(8, 8, 4), 256>>>(pA, NH, pTREC, NH, pGP, NH, NH, T * B, 1600);
    k_reduce<<<(NH * NH + 255) / 256, 256>>>(pGP, gr, NH * NH, 4);

    // go = LR * EF^T @ Z    [20 x 512], K = 6400
    k_gemmT<<<dim3(8, 1, 8), 256>>>(pEF, NO, pZ, NH, pGP, NO, NH, T * B, 800);
    k_reduce<<<(NO * NH + 255) / 256, 256>>>(pGP, go, NO * NH, 8);
}

// round 4
// speedup vs baseline: 3.6059x; 1.0710x over previous
#include <cuda_runtime.h>

#define B   64
#define T   100
#define NI  700
#define NH  512
#define NO  20
#define TAUc 0.6f
#define KAPc 0.6f
#define THRc 0.6f
#define LRc  0.05f

#define NBLK 128   // persistent forward blocks

// ---------------- persistent device scratch ----------------
__device__ float g_XP  [T*B*NH];   // x @ W1^T, rows m = t*B+b
__device__ float g_TIN [T*B*NI];
__device__ float g_TREC[T*B*NH];
__device__ float g_HT  [T*B*NH];
__device__ float g_Z   [T*B*NH];
__device__ float g_S   [T*B*NO];   // Z @ wout^T
__device__ float g_ERR [T*B*NO];
__device__ float g_EF  [T*B*NO];
__device__ float g_A   [T*B*NH];
__device__ float g_gpart[8*512*700];
__device__ unsigned g_barc, g_barg;

// ---------------- tin scan (no recurrence) + barrier init ----------------
__global__ void k_tin(const float* __restrict__ x) {
    int n = blockIdx.x * blockDim.x + threadIdx.x;
    if (n == 0) { g_barc = 0u; g_barg = 0u; }
    if (n >= B * NI) return;
    int b = n / NI, i = n - b * NI;
    float tv = 0.f;
    for (int t = 0; t < T; t++) {
        tv = TAUc * tv + x[(b * T + t) * NI + i];
        g_TIN[((size_t)t * B + b) * NI + i] = tv;
    }
}

// ---------------- Xproj = X @ W1^T : [6400,512], K=700, 128x128 tiles ----------------
__global__ __launch_bounds__(256) void k_gemmX(const float* __restrict__ x,
                                               const float* __restrict__ w1) {
    __shared__ float As[16][129];   // [k][m], 129 stride: conflict-free transposed stores
    __shared__ float Bs[16][129];   // [k][n]
    int m0 = blockIdx.y * 128, n0 = blockIdx.x * 128;
    int tid = threadIdx.x, tx = tid & 15, ty = tid >> 4;
    float acc[8][8] = {};

    for (int k0 = 0; k0 < NI; k0 += 16) {
#pragma unroll
        for (int rep = 0; rep < 2; rep++) {
            int f = tid + rep * 256;        // 0..511
            int mm = f >> 2, kq = f & 3;
            int kg = k0 + kq * 4;
            // A tile: X rows in time-major m = t*B+b
            {
                int m = m0 + mm, t = m >> 6, b = m & 63;
                const float* xp = &x[((size_t)b * T + t) * NI + kg];
                float4 v;
                if (kg + 3 < NI) v = *(const float4*)xp;
                else {
                    v.x = (kg + 0 < NI) ? xp[0] : 0.f;
                    v.y = (kg + 1 < NI) ? xp[1] : 0.f;
                    v.z = (kg + 2 < NI) ? xp[2] : 0.f;
                    v.w = (kg + 3 < NI) ? xp[3] : 0.f;
                }
                As[kq * 4 + 0][mm] = v.x; As[kq * 4 + 1][mm] = v.y;
                As[kq * 4 + 2][mm] = v.z; As[kq * 4 + 3][mm] = v.w;
            }
            // B tile: w1[n, k]
            {
                int n = n0 + mm;
                const float* wp = &w1[(size_t)n * NI + kg];
                float4 v;
                if (kg + 3 < NI) v = *(const float4*)wp;
                else {
                    v.x = (kg + 0 < NI) ? wp[0] : 0.f;
                    v.y = (kg + 1 < NI) ? wp[1] : 0.f;
                    v.z = (kg + 2 < NI) ? wp[2] : 0.f;
                    v.w = (kg + 3 < NI) ? wp[3] : 0.f;
                }
                Bs[kq * 4 + 0][mm] = v.x; Bs[kq * 4 + 1][mm] = v.y;
                Bs[kq * 4 + 2][mm] = v.z; Bs[kq * 4 + 3][mm] = v.w;
            }
        }
        __syncthreads();
#pragma unroll
        for (int k = 0; k < 16; k++) {
            float a[8], bb[8];
#pragma unroll
            for (int i = 0; i < 4; i++) {
                a[i]      = As[k][ty * 4 + i];
                a[4 + i]  = As[k][64 + ty * 4 + i];
                bb[i]     = Bs[k][tx * 4 + i];
                bb[4 + i] = Bs[k][64 + tx * 4 + i];
            }
#pragma unroll
            for (int i = 0; i < 8; i++)
#pragma unroll
                for (int j = 0; j < 8; j++) acc[i][j] += a[i] * bb[j];
        }
        __syncthreads();
    }
#pragma unroll
    for (int i = 0; i < 8; i++) {
        int m = m0 + ((i < 4) ? ty * 4 + i : 64 + ty * 4 + (i - 4));
#pragma unroll
        for (int j = 0; j < 8; j++) {
            int n = n0 + ((j < 4) ? tx * 4 + j : 64 + tx * 4 + (j - 4));
            g_XP[(size_t)m * NH + n] = acc[i][j];
        }
    }
}

// ---------------- persistent forward: 100 steps, 1 grid barrier/step ----------------
__global__ void k_forward(const float* __restrict__ wrec) {
    extern __shared__ float Ws[];   // [512][32] = Wrec[:, r0:r0+32]
    int bg = blockIdx.x & 7, rg = blockIdx.x >> 3;
    int tid = threadIdx.x, lane = tid & 31, ty = tid >> 5;
    int b = bg * 8 + ty;
    int r0 = rg * 32;
    int r = r0 + lane;

    for (int idx = tid; idx < NH * 32; idx += 256)
        Ws[idx] = wrec[(idx >> 5) * NH + r0 + (idx & 31)];
    __syncthreads();

    float hm = 0.f, tr = 0.f, zs = 0.f;

    for (int t = 0; t < T; t++) {
        float acc = 0.f;
        if (t > 0) {
            const float* zp = g_Z + ((size_t)(t - 1) * B + b) * NH;
            float zv[16];
#pragma unroll
            for (int c = 0; c < 16; c++) zv[c] = __ldcg(zp + c * 32 + lane);
#pragma unroll
            for (int c = 0; c < 16; c++) {
                unsigned m = __ballot_sync(0xffffffffu, zv[c] != 0.f);
                while (m) {
                    int j = c * 32 + (__ffs(m) - 1);
                    m &= m - 1;
                    acc += Ws[j * 32 + lane];
                }
            }
        }
        float hid = __ldcg(&g_XP[((size_t)t * B + b) * NH + r]) + acc;
        hm = TAUc * hm * (1.f - zs) + hid;
        float z  = (hm >= THRc) ? 1.f : 0.f;
        float ht = TAUc * fmaxf(0.f, 1.f - fabsf((hm - THRc) * (1.f / THRc)));
        tr = TAUc * tr + zs;
        size_t o = ((size_t)t * B + b) * NH + r;
        g_Z[o] = z; g_HT[o] = ht; g_TREC[o] = tr;
        zs = z;

        __syncthreads();
        if (tid == 0) {
            __threadfence();
            unsigned gen = *(volatile unsigned*)&g_barg;
            if (atomicAdd(&g_barc, 1u) == NBLK - 1) {
                g_barc = 0u;
                __threadfence();
                atomicAdd(&g_barg, 1u);
            } else {
                while (*(volatile unsigned*)&g_barg == gen) { }
            }
        }
        __syncthreads();
    }
}

// ---------------- S[m,o] = Z[m,:] . wout[o,:]  (parallel over all m) ----------------
__global__ __launch_bounds__(256) void k_s(const float* __restrict__ wout) {
    __shared__ float ws[NO * NH];   // 40KB
    int m0 = blockIdx.x * 64;
    int tid = threadIdx.x, w = tid >> 5, lane = tid & 31;
    for (int i = tid; i < NO * NH; i += 256) ws[i] = wout[i];
    __syncthreads();
#pragma unroll 1
    for (int rr = 0; rr < 8; rr++) {
        int m = m0 + w * 8 + rr;
        float zv[16];
#pragma unroll
        for (int c = 0; c < 16; c++) zv[c] = g_Z[(size_t)m * NH + c * 32 + lane];
        float acc[NO];
#pragma unroll
        for (int o = 0; o < NO; o++) acc[o] = 0.f;
#pragma unroll
        for (int c = 0; c < 16; c++) {
            float z = zv[c];
#pragma unroll
            for (int o = 0; o < NO; o++) acc[o] += z * ws[o * NH + c * 32 + lane];
        }
#pragma unroll
        for (int o = 0; o < NO; o++) {
            float s = acc[o];
#pragma unroll
            for (int off = 16; off; off >>= 1) s += __shfl_xor_sync(0xffffffffu, s, off);
            if (lane == 0) g_S[(size_t)m * NO + o] = s;
        }
    }
}

// ---------------- scalar scan: output LIF forward + reverse kappa filter ----------------
__global__ void k_scan(const float* __restrict__ label, float* __restrict__ out) {
    int n = blockIdx.x * 256 + threadIdx.x;
    if (n >= B * NO) return;
    int b = n / NO, o = n - b * NO;
    float om = 0.f, os = 0.f;
    for (int t = 0; t < T; t++) {
        float s = g_S[((size_t)t * B + b) * NO + o];
        om = TAUc * om * (1.f - os) + s;
        os = (om >= THRc) ? 1.f : 0.f;
        float err = os - label[((size_t)b * T + t) * NO + o];
        out[((size_t)b * T + t) * NO + o] = os;
        g_ERR[((size_t)t * B + b) * NO + o] = err;
    }
    float ef = 0.f;
    for (int t = T - 1; t >= 0; t--) {
        ef = g_ERR[((size_t)t * B + b) * NO + o] + KAPc * ef;
        g_EF[((size_t)t * B + b) * NO + o] = ef;
    }
}

// ---------------- A[m,r] = (EF[m,:] . wout[:,r]) * HT[m,r] ----------------
__global__ void k_A(const float* __restrict__ wout) {
    int gid = blockIdx.x * 256 + threadIdx.x;
    if (gid >= T * B * NH) return;
    int m = gid >> 9;
    int r = gid & (NH - 1);
    const float* ef = g_EF + (size_t)m * NO;
    float L = 0.f;
#pragma unroll
    for (int o = 0; o < NO; o++) L += ef[o] * wout[o * NH + r];
    g_A[gid] = L * g_HT[gid];
}

// ---------------- C = A^T B, 128x128 tiles, split-K partials ----------------
// A: [K, M] (sA), B: [K, N] (sB). M must be a multiple of 128.
__global__ __launch_bounds__(256) void k_gemm128T(const float* __restrict__ A, int sA,
                                                  const float* __restrict__ Bm, int sB,
                                                  float* __restrict__ Cp,
                                                  int M, int N, int kchunk) {
    __shared__ float As[16][128];
    __shared__ float Bs[16][128];
    int n0 = blockIdx.x * 128, m0 = blockIdx.y * 128;
    int z = blockIdx.z;
    int k0s = z * kchunk;
    int tid = threadIdx.x, tx = tid & 15, ty = tid >> 4;
    float acc[8][8] = {};

    for (int k0 = k0s; k0 < k0s + kchunk; k0 += 16) {
#pragma unroll
        for (int rep = 0; rep < 2; rep++) {
            int f = tid + rep * 256;
            int kk = f >> 5, c4 = (f & 31) * 4;
            *(float4*)&As[kk][c4] = *(const float4*)&A[(size_t)(k0 + kk) * sA + m0 + c4];
            int n = n0 + c4;
            const float* bp = &Bm[(size_t)(k0 + kk) * sB + n];
            float4 bv;
            if (n + 3 < N) bv = *(const float4*)bp;
            else {
                bv.x = (n + 0 < N) ? bp[0] : 0.f;
                bv.y = (n + 1 < N) ? bp[1] : 0.f;
                bv.z = (n + 2 < N) ? bp[2] : 0.f;
                bv.w = (n + 3 < N) ? bp[3] : 0.f;
            }
            *(float4*)&Bs[kk][c4] = bv;
        }
        __syncthreads();
#pragma unroll
        for (int k = 0; k < 16; k++) {
            float a[8], bb[8];
            *(float4*)&a[0]  = *(float4*)&As[k][ty * 4];
            *(float4*)&a[4]  = *(float4*)&As[k][64 + ty * 4];
            *(float4*)&bb[0] = *(float4*)&Bs[k][tx * 4];
            *(float4*)&bb[4] = *(float4*)&Bs[k][64 + tx * 4];
#pragma unroll
            for (int i = 0; i < 8; i++)
#pragma unroll
                for (int j = 0; j < 8; j++) acc[i][j] += a[i] * bb[j];
        }
        __syncthreads();
    }
    float* C = Cp + (size_t)z * M * N;
#pragma unroll
    for (int i = 0; i < 8; i++) {
        int m = m0 + ((i < 4) ? ty * 4 + i : 64 + ty * 4 + (i - 4));
#pragma unroll
        for (int j = 0; j < 8; j++) {
            int n = n0 + ((j < 4) ? tx * 4 + j : 64 + tx * 4 + (j - 4));
            if (n < N) C[(size_t)m * N + n] = acc[i][j];
        }
    }
}

// ---------------- small 64x64 A^T B for go ----------------
__global__ void k_gemmT64(const float* __restrict__ A, int sA,
                          const float* __restrict__ Bm, int sB,
                          float* __restrict__ Cp,
                          int M, int N, int K, int kchunk) {
    __shared__ float As[16][64];
    __shared__ float Bs[16][64];
    int m0 = blockIdx.y * 64, n0 = blockIdx.x * 64;
    int z = blockIdx.z;
    int k0s = z * kchunk;
    int k0e = min(K, k0s + kchunk);
    int tid = threadIdx.x;
    int tx = tid & 15, ty = tid >> 4;
    float acc[4][4] = {};
    for (int k0 = k0s; k0 < k0e; k0 += 16) {
#pragma unroll
        for (int rep = 0; rep < 4; rep++) {
            int e = tid + rep * 256;
            int mm = e & 63, kk = e >> 6;
            int mg = m0 + mm;
            As[kk][mm] = (mg < M) ? A[(size_t)(k0 + kk) * sA + mg] : 0.f;
            int ng = n0 + mm;
            Bs[kk][mm] = (ng < N) ? Bm[(size_t)(k0 + kk) * sB + ng] : 0.f;
        }
        __syncthreads();
#pragma unroll
        for (int k = 0; k < 16; k++) {
            float a[4], bb[4];
#pragma unroll
            for (int i = 0; i < 4; i++) a[i]  = As[k][ty * 4 + i];
#pragma unroll
            for (int j = 0; j < 4; j++) bb[j] = Bs[k][tx * 4 + j];
#pragma unroll
            for (int i = 0; i < 4; i++)
#pragma unroll
                for (int j = 0; j < 4; j++) acc[i][j] += a[i] * bb[j];
        }
        __syncthreads();
    }
    float* C = Cp + (size_t)z * M * N;
#pragma unroll
    for (int i = 0; i < 4; i++) {
        int m = m0 + ty * 4 + i;
        if (m < M) {
#pragma unroll
            for (int j = 0; j < 4; j++) {
                int n = n0 + tx * 4 + j;
                if (n < N) C[(size_t)m * N + n] = acc[i][j];
            }
        }
    }
}

__global__ void k_reduce(const float* __restrict__ Cp, float* __restrict__ out,
                         int MN, int KS) {
    int i = blockIdx.x * 256 + threadIdx.x;
    if (i >= MN) return;
    float s = 0.f;
    for (int z = 0; z < KS; z++) s += Cp[(size_t)z * MN + i];
    out[i] = LRc * s;
}

// ---------------- launch ----------------
extern "C" void kernel_launch(void* const* d_in, const int* in_sizes, int n_in,
                              void* d_out, int out_size) {
    const float* x     = (const float*)d_in[0];
    const float* label = (const float*)d_in[1];
    const float* w1    = (const float*)d_in[3];
    const float* wrec  = (const float*)d_in[4];
    const float* wout  = (const float*)d_in[5];
    float* out = (float*)d_out;
    float* gf = out + B * T * NO;          // [NH, NI]
    float* gr = gf + NH * NI;              // [NH, NH]
    float* go = gr + NH * NH;              // [NO, NH]

    static int attr_done = 0;
    if (!attr_done) {
        cudaFuncSetAttribute(k_forward, cudaFuncAttributeMaxDynamicSharedMemorySize,
                             NH * 32 * (int)sizeof(float));
        attr_done = 1;
    }

    float *pA, *pTIN, *pTREC, *pZ, *pEF, *pGP;
    cudaGetSymbolAddress((void**)&pA,    g_A);
    cudaGetSymbolAddress((void**)&pTIN,  g_TIN);
    cudaGetSymbolAddress((void**)&pTREC, g_TREC);
    cudaGetSymbolAddress((void**)&pZ,    g_Z);
    cudaGetSymbolAddress((void**)&pEF,   g_EF);
    cudaGetSymbolAddress((void**)&pGP,   g_gpart);

    k_tin<<<(B * NI + 255) / 256, 256>>>(x);
    k_gemmX<<<dim3(4, 50), 256>>>(x, w1);                  // [6400,512] K=700
    k_forward<<<NBLK, 256, NH * 32 * sizeof(float)>>>(wrec);
    k_s<<<100, 256>>>(wout);
    k_scan<<<5, 256>>>(label, out);
    k_A<<<(T * B * NH + 255) / 256, 256>>>(wout);

    // gf = LR * A^T @ TIN   [512 x 700], K=6400, splitK 8
    k_gemm128T<<<dim3(6, 4, 8), 256>>>(pA, NH, pTIN, NI, pGP, NH, NI, 800);
    k_reduce<<<(NH * NI + 255) / 256, 256>>>(pGP, gf, NH * NI, 8);

    // gr = LR * A^T @ TREC  [512 x 512], K=6400, splitK 8
    k_gemm128T<<<dim3(4, 4, 8), 256>>>(pA, NH, pTREC, NH, pGP, NH, NH, 800);
    k_reduce<<<(NH * NH + 255) / 256, 256>>>(pGP, gr, NH * NH, 8);

    // go = LR * EF^T @ Z    [20 x 512], K=6400, splitK 8
    k_gemmT64<<<dim3(8, 1, 8), 256>>>(pEF, NO, pZ, NH, pGP, NO, NH, T * B, 800);
    k_reduce<<<(NO * NH + 255) / 256, 256>>>(pGP, go, NO * NH, 8);
}